// round 14
// baseline (speedup 1.0000x reference)
#include <cuda_runtime.h>
#include <cuda_fp16.h>
#include <cstdint>

#define Bb 2
#define Ss 2048
#define Dd 4096
#define Hh 32
#define HKVn 8
#define HDd 128
#define Mm (Bb*Ss)
#define NKV (HKVn*HDd)

// Scratch (device globals: allocation-free)
__device__ float  g_q[(size_t)Mm * Dd];       // f32 q (pre-rope)
__device__ float  g_k[(size_t)Mm * NKV];      // f32 k (pre-rope)
__device__ __half g_qh[(size_t)Mm * Dd];      // fp16 q (post-rope, scaled)
__device__ __half g_kh[(size_t)Mm * NKV];     // fp16 k (post-rope)
__device__ __half g_vh[(size_t)Mm * NKV];     // fp16 v
__device__ __half g_ctxh[(size_t)Mm * Dd];
__device__ __half g_hsh[(size_t)Mm * Dd];     // fp16 hidden_states
__device__ __half g_wqt[(size_t)Dd * Dd];     // fp16 W^T (K-major, [N][K])
__device__ __half g_wkt[(size_t)NKV * Dd];
__device__ __half g_wvt[(size_t)NKV * Dd];
__device__ __half g_wot[(size_t)Dd * Dd];

__device__ __forceinline__ void mma_f16(float* c, const unsigned* a, const unsigned* b) {
    asm volatile(
        "mma.sync.aligned.m16n8k16.row.col.f32.f16.f16.f32 "
        "{%0,%1,%2,%3}, {%4,%5,%6,%7}, {%8,%9}, {%0,%1,%2,%3};"
        : "+f"(c[0]), "+f"(c[1]), "+f"(c[2]), "+f"(c[3])
        : "r"(a[0]), "r"(a[1]), "r"(a[2]), "r"(a[3]), "r"(b[0]), "r"(b[1]));
}

__device__ __forceinline__ void ldsm4(unsigned& r0, unsigned& r1, unsigned& r2,
                                      unsigned& r3, unsigned addr) {
    asm volatile("ldmatrix.sync.aligned.m8n8.x4.shared.b16 {%0,%1,%2,%3}, [%4];"
                 : "=r"(r0), "=r"(r1), "=r"(r2), "=r"(r3) : "r"(addr));
}
__device__ __forceinline__ void ldsm4t(unsigned& r0, unsigned& r1, unsigned& r2,
                                       unsigned& r3, unsigned addr) {
    asm volatile("ldmatrix.sync.aligned.m8n8.x4.trans.shared.b16 {%0,%1,%2,%3}, [%4];"
                 : "=r"(r0), "=r"(r1), "=r"(r2), "=r"(r3) : "r"(addr));
}

__device__ __forceinline__ void cp16s(uint32_t dst, const void* src) {
    asm volatile("cp.async.cg.shared.global [%0], [%1], 16;" :: "r"(dst), "l"(src));
}
__device__ __forceinline__ void cp_commit() {
    asm volatile("cp.async.commit_group;" ::: "memory");
}
template <int N>
__device__ __forceinline__ void cp_wait() {
    asm volatile("cp.async.wait_group %0;" :: "n"(N) : "memory");
}

// ---------------------------------------------------------------------------
// Pre-pass: f32 -> fp16 copy, and f32 -> fp16 transpose (W[K,N] -> Wt[N,K]).
// ---------------------------------------------------------------------------
__global__ void cvt_h_k(const float4* __restrict__ in, uint2* __restrict__ out, int n4) {
    int i = blockIdx.x * blockDim.x + threadIdx.x;
    if (i >= n4) return;
    float4 v = in[i];
    __half2 h0 = __floats2half2_rn(v.x, v.y);
    __half2 h1 = __floats2half2_rn(v.z, v.w);
    uint2 u = {*(unsigned*)&h0, *(unsigned*)&h1};
    out[i] = u;
}

__global__ void transpose_cvt_k(const float* __restrict__ in, __half* __restrict__ out,
                                int R, int C) {   // in[R][C] -> out[C][R]
    __shared__ float t[32][33];
    int x = blockIdx.x * 32 + threadIdx.x;
    int y = blockIdx.y * 32 + threadIdx.y;
#pragma unroll
    for (int j = 0; j < 32; j += 8)
        t[threadIdx.y + j][threadIdx.x] = in[(size_t)(y + j) * C + x];
    __syncthreads();
    int x2 = blockIdx.y * 32 + threadIdx.x;
    int y2 = blockIdx.x * 32 + threadIdx.y;
#pragma unroll
    for (int j = 0; j < 32; j += 8)
        out[(size_t)(y2 + j) * R + x2] = __float2half_rn(t[threadIdx.x][threadIdx.y + j]);
}

// ---------------------------------------------------------------------------
// fp16 GEMM (R10 config): C = A[M,K] @ Bt[N,K]^T; A/Bt fp16 row-major.
// Block 128x128, BK=32, 256 threads (8 warps, 64x32 warp tile), occupancy 2.
// 3-stage cp.async ring (lookahead 1), ldmatrix frags.
// ---------------------------------------------------------------------------
#define GA_STRIDE 40
#define GA_STAGE_B (128 * GA_STRIDE * 2)          // bytes per stage per operand
#define G_SMEM_BYTES (6 * GA_STAGE_B)             // 61440

__global__ __launch_bounds__(256, 2) void gemm_f16_k(
    const __half* __restrict__ A, const __half* __restrict__ Bt,
    float* __restrict__ Cf, __half* __restrict__ Ch, int M, int N, int K) {
    extern __shared__ char smem[];
    const uint32_t sb = (uint32_t)__cvta_generic_to_shared(smem);
    const uint32_t sbA = sb, sbB = sb + 3 * GA_STAGE_B;

    const int bm = blockIdx.y * 128, bn = blockIdx.x * 128;
    const int tid = threadIdx.x, warp = tid >> 5, lane = tid & 31;
    const int wm = (warp >> 2) * 64, wn = (warp & 3) * 32;
    const int g = lane >> 2, t = lane & 3;

    const int arow = lane & 15, acol = (lane >> 4) << 3;
    const int brow = (((lane >> 4) & 1) << 3) + (lane & 7);
    const int bcol = ((lane >> 3) & 1) << 3;

    int rr[2], cu[2];
#pragma unroll
    for (int j = 0; j < 2; j++) {
        int id = tid + j * 256;
        rr[j] = id >> 2;
        cu[j] = (id & 3) << 3;
    }

    float acc[4][4][4];
#pragma unroll
    for (int mt = 0; mt < 4; mt++)
#pragma unroll
        for (int nt = 0; nt < 4; nt++)
#pragma unroll
            for (int i = 0; i < 4; i++) acc[mt][nt][i] = 0.f;

    auto load_stage = [&](int k0, int s) {
#pragma unroll
        for (int j = 0; j < 2; j++) {
            cp16s(sbA + s * GA_STAGE_B + (rr[j] * GA_STRIDE + cu[j]) * 2,
                  A + (size_t)(bm + rr[j]) * K + k0 + cu[j]);
            cp16s(sbB + s * GA_STAGE_B + (rr[j] * GA_STRIDE + cu[j]) * 2,
                  Bt + (size_t)(bn + rr[j]) * K + k0 + cu[j]);
        }
        cp_commit();
    };

    load_stage(0, 0);

    const int niter = K / 32;
    for (int it = 0; it < niter; it++) {
        if (it + 1 < niter) { load_stage((it + 1) * 32, (it + 1) % 3); cp_wait<1>(); }
        else cp_wait<0>();
        __syncthreads();

        const uint32_t cA = sbA + (it % 3) * GA_STAGE_B;
        const uint32_t cB = sbB + (it % 3) * GA_STAGE_B;
#pragma unroll
        for (int kk = 0; kk < 32; kk += 16) {
            unsigned a[4][4], b[2][4];
#pragma unroll
            for (int mt = 0; mt < 4; mt++)
                ldsm4(a[mt][0], a[mt][1], a[mt][2], a[mt][3],
                      cA + ((wm + mt * 16 + arow) * GA_STRIDE + kk + acol) * 2);
#pragma unroll
            for (int p = 0; p < 2; p++)
                ldsm4(b[p][0], b[p][1], b[p][2], b[p][3],
                      cB + ((wn + p * 16 + brow) * GA_STRIDE + kk + bcol) * 2);
#pragma unroll
            for (int mt = 0; mt < 4; mt++)
#pragma unroll
                for (int nt = 0; nt < 4; nt++) {
                    unsigned bb[2] = {b[nt >> 1][(nt & 1) * 2],
                                      b[nt >> 1][(nt & 1) * 2 + 1]};
                    mma_f16(acc[mt][nt], a[mt], bb);
                }
        }
        __syncthreads();
    }

#pragma unroll
    for (int mt = 0; mt < 4; mt++)
#pragma unroll
        for (int nt = 0; nt < 4; nt++) {
            int r0 = bm + wm + mt * 16 + g;
            int c0 = bn + wn + nt * 8 + 2 * t;
            if (Ch) {
                *(__half2*)&Ch[(size_t)r0 * N + c0] =
                    __floats2half2_rn(acc[mt][nt][0], acc[mt][nt][1]);
                *(__half2*)&Ch[(size_t)(r0 + 8) * N + c0] =
                    __floats2half2_rn(acc[mt][nt][2], acc[mt][nt][3]);
            } else {
                float2 v0 = {acc[mt][nt][0], acc[mt][nt][1]};
                float2 v1 = {acc[mt][nt][2], acc[mt][nt][3]};
                *(float2*)&Cf[(size_t)r0 * N + c0] = v0;
                *(float2*)&Cf[(size_t)(r0 + 8) * N + c0] = v1;
            }
        }
}

// ---------------------------------------------------------------------------
// RoPE (NeoX, half=64): reads f32 [B*S, nh, 128], writes fp16 (scale folded).
// ---------------------------------------------------------------------------
__global__ void rope_h_k(const float* __restrict__ x, __half* __restrict__ out,
                         const int* __restrict__ pos, int nh, int total, float scale) {
    int i = blockIdx.x * blockDim.x + threadIdx.x;
    if (i >= total) return;
    int j = i & 63;
    int h = (i >> 6) % nh;
    int row = i / (64 * nh);
    float p = (float)pos[row];
    float fr = p * exp2f(-(float)j * 0.20762050593046062f);
    float sn, cs;
    sincosf(fr, &sn, &cs);
    size_t base = ((size_t)row * nh + h) * 128 + j;
    float v1 = x[base] * scale, v2 = x[base + 64] * scale;
    out[base] = __float2half_rn(v1 * cs - v2 * sn);
    out[base + 64] = __float2half_rn(v2 * cs + v1 * sn);
}

// ---------------------------------------------------------------------------
// Flash attention v2: Q-tile 128 (256 threads, 8 warps), K-tile 64,
// cp.async double-buffered K/V, causal + key mask, GQA.
// Grid: (S/128 q-tiles, B*H).
// ---------------------------------------------------------------------------
#define FQ_STR 136
#define FP_STR 72
#define F_TILE (64 * FQ_STR)                 // one K or V stage (halves)
#define F_KV (128 * FQ_STR)                  // K stages start (halves)
#define F_P (F_KV + 4 * F_TILE)              // P tile start (halves)
#define F_HALVES (F_P + 128 * FP_STR)
#define F_SMEM_BYTES (F_HALVES * 2 + 128 * 4)

__global__ __launch_bounds__(256) void flash_k(
    const __half* __restrict__ q, const __half* __restrict__ k,
    const __half* __restrict__ v, const int* __restrict__ am,
    __half* __restrict__ ctx) {
    extern __shared__ char smem[];
    __half* Qs = (__half*)smem;
    int* km = (int*)(smem + F_HALVES * 2);   // km[2][64]
    const uint32_t sb = (uint32_t)__cvta_generic_to_shared(smem);

    const int bh = blockIdx.y;
    const int b = bh >> 5, h = bh & 31, hk = h >> 2;
    const int q0 = blockIdx.x * 128;
    const int tid = threadIdx.x, warp = tid >> 5, lane = tid & 31;
    const int g = lane >> 2, t = lane & 3;
    const int arow = lane & 15, acol = (lane >> 4) << 3;
    const int brow = (((lane >> 4) & 1) << 3) + (lane & 7);
    const int bcol = ((lane >> 3) & 1) << 3;

    // Load Q tile (128x128 fp16): 2048 16B chunks / 256 threads = 8 each
#pragma unroll
    for (int i = 0; i < 8; i++) {
        int idx = tid + i * 256;
        int r = idx >> 4, c = (idx & 15) << 3;
        *(uint4*)&Qs[r * FQ_STR + c] =
            *(const uint4*)(q + ((size_t)(b * Ss + q0 + r) * Hh + h) * HDd + c);
    }

    // K/V stage loader: 64x128 halves = 1024 chunks, 4 per thread per tensor
    auto load_kv = [&](int kt, int s) {
#pragma unroll
        for (int i = 0; i < 4; i++) {
            int idx = tid + i * 256;
            int r = idx >> 4, c = (idx & 15) << 3;
            size_t base = ((size_t)(b * Ss + kt * 64 + r) * HKVn + hk) * HDd + c;
            cp16s(sb + (F_KV + s * F_TILE + r * FQ_STR + c) * 2, k + base);
            cp16s(sb + (F_KV + (2 + s) * F_TILE + r * FQ_STR + c) * 2, v + base);
        }
        if (tid < 64) km[s * 64 + tid] = am[b * Ss + kt * 64 + tid];
        cp_commit();
    };

    float o[16][4];
#pragma unroll
    for (int nt = 0; nt < 16; nt++)
#pragma unroll
        for (int i = 0; i < 4; i++) o[nt][i] = 0.f;
    float mrow0 = -1e30f, mrow1 = -1e30f, lrow0 = 0.f, lrow1 = 0.f;

    const int nkt = 2 * blockIdx.x + 2;
    const int qrow0 = q0 + warp * 16 + g, qrow1 = qrow0 + 8;
    const int r0 = warp * 16;

    load_kv(0, 0);

    for (int kt = 0; kt < nkt; kt++) {
        const int s = kt & 1;
        if (kt + 1 < nkt) { load_kv(kt + 1, s ^ 1); cp_wait<1>(); }
        else cp_wait<0>();
        __syncthreads();

        const uint32_t sK = sb + (F_KV + s * F_TILE) * 2;
        const uint32_t sV = sb + (F_KV + (2 + s) * F_TILE) * 2;

        // S = Q K^T : 16 q-rows x 64 keys per warp
        float sc[8][4];
#pragma unroll
        for (int nt = 0; nt < 8; nt++)
#pragma unroll
            for (int i = 0; i < 4; i++) sc[nt][i] = 0.f;
#pragma unroll
        for (int d16 = 0; d16 < 128; d16 += 16) {
            unsigned a[4], bq[4][4];
            ldsm4(a[0], a[1], a[2], a[3],
                  sb + ((r0 + arow) * FQ_STR + d16 + acol) * 2);
#pragma unroll
            for (int p = 0; p < 4; p++)
                ldsm4(bq[p][0], bq[p][1], bq[p][2], bq[p][3],
                      sK + ((p * 16 + brow) * FQ_STR + d16 + bcol) * 2);
#pragma unroll
            for (int nt = 0; nt < 8; nt++) {
                unsigned bb[2] = {bq[nt >> 1][(nt & 1) * 2],
                                  bq[nt >> 1][(nt & 1) * 2 + 1]};
                mma_f16(sc[nt], a, bb);
            }
        }

        // Causal + key mask, online softmax
        float mx0 = -1e30f, mx1 = -1e30f;
#pragma unroll
        for (int nt = 0; nt < 8; nt++) {
            int cl = nt * 8 + 2 * t;
            int c0 = kt * 64 + cl;
            int m0 = km[s * 64 + cl], m1 = km[s * 64 + cl + 1];
            if (c0 > qrow0 || m0 == 0) sc[nt][0] = -1e30f;
            if (c0 + 1 > qrow0 || m1 == 0) sc[nt][1] = -1e30f;
            if (c0 > qrow1 || m0 == 0) sc[nt][2] = -1e30f;
            if (c0 + 1 > qrow1 || m1 == 0) sc[nt][3] = -1e30f;
            mx0 = fmaxf(mx0, fmaxf(sc[nt][0], sc[nt][1]));
            mx1 = fmaxf(mx1, fmaxf(sc[nt][2], sc[nt][3]));
        }
        mx0 = fmaxf(mx0, __shfl_xor_sync(0xffffffffu, mx0, 1));
        mx0 = fmaxf(mx0, __shfl_xor_sync(0xffffffffu, mx0, 2));
        mx1 = fmaxf(mx1, __shfl_xor_sync(0xffffffffu, mx1, 1));
        mx1 = fmaxf(mx1, __shfl_xor_sync(0xffffffffu, mx1, 2));

        float nm0 = fmaxf(mrow0, mx0), nm1 = fmaxf(mrow1, mx1);
        float al0 = __expf(mrow0 - nm0), al1 = __expf(mrow1 - nm1);
        mrow0 = nm0; mrow1 = nm1;

        float sum0 = 0.f, sum1 = 0.f;
#pragma unroll
        for (int nt = 0; nt < 8; nt++) {
            sc[nt][0] = __expf(sc[nt][0] - nm0);
            sc[nt][1] = __expf(sc[nt][1] - nm0);
            sc[nt][2] = __expf(sc[nt][2] - nm1);
            sc[nt][3] = __expf(sc[nt][3] - nm1);
            sum0 += sc[nt][0] + sc[nt][1];
            sum1 += sc[nt][2] + sc[nt][3];
        }
        sum0 += __shfl_xor_sync(0xffffffffu, sum0, 1);
        sum0 += __shfl_xor_sync(0xffffffffu, sum0, 2);
        sum1 += __shfl_xor_sync(0xffffffffu, sum1, 1);
        sum1 += __shfl_xor_sync(0xffffffffu, sum1, 2);
        lrow0 = lrow0 * al0 + sum0;
        lrow1 = lrow1 * al1 + sum1;

#pragma unroll
        for (int nt = 0; nt < 16; nt++) {
            o[nt][0] *= al0; o[nt][1] *= al0;
            o[nt][2] *= al1; o[nt][3] *= al1;
        }

        // Stage P (fp16) to warp-private smem rows
        __syncwarp();
#pragma unroll
        for (int nt = 0; nt < 8; nt++) {
            *(__half2*)&((__half*)smem)[F_P + (r0 + g) * FP_STR + nt * 8 + 2 * t] =
                __floats2half2_rn(sc[nt][0], sc[nt][1]);
            *(__half2*)&((__half*)smem)[F_P + (r0 + g + 8) * FP_STR + nt * 8 + 2 * t] =
                __floats2half2_rn(sc[nt][2], sc[nt][3]);
        }
        __syncwarp();

        // O += P @ V  (keys 64 in 4 steps of 16; V^T frags via ldmatrix.trans)
#pragma unroll
        for (int kk = 0; kk < 64; kk += 16) {
            unsigned a[4], bv[8][4];
            ldsm4(a[0], a[1], a[2], a[3],
                  sb + (F_P + (r0 + arow) * FP_STR + kk + acol) * 2);
#pragma unroll
            for (int p = 0; p < 8; p++)
                ldsm4t(bv[p][0], bv[p][1], bv[p][2], bv[p][3],
                       sV + ((kk + arow) * FQ_STR + p * 16 + acol) * 2);
#pragma unroll
            for (int nt = 0; nt < 16; nt++) {
                unsigned bb[2] = {bv[nt >> 1][(nt & 1) * 2],
                                  bv[nt >> 1][(nt & 1) * 2 + 1]};
                mma_f16(o[nt], a, bb);
            }
        }
        __syncthreads();   // all warps done with stage s before it is reloaded
    }

    // Finalize, write ctx fp16 [B*S, H*HD]
    float il0 = 1.f / lrow0, il1 = 1.f / lrow1;
    int rq = q0 + r0 + g;
#pragma unroll
    for (int nt = 0; nt < 16; nt++) {
        int c = h * 128 + nt * 8 + 2 * t;
        *(__half2*)&ctx[(size_t)(b * Ss + rq) * Dd + c] =
            __floats2half2_rn(o[nt][0] * il0, o[nt][1] * il0);
        *(__half2*)&ctx[(size_t)(b * Ss + rq + 8) * Dd + c] =
            __floats2half2_rn(o[nt][2] * il1, o[nt][3] * il1);
    }
}

// ---------------------------------------------------------------------------
extern "C" void kernel_launch(void* const* d_in, const int* in_sizes, int n_in,
                              void* d_out, int out_size) {
    const float* hs = (const float*)d_in[0];
    const int* pos = (const int*)d_in[1];
    const int* am = (const int*)d_in[2];
    const float* Wq = (const float*)d_in[3];
    const float* Wk = (const float*)d_in[4];
    const float* Wv = (const float*)d_in[5];
    const float* Wo = (const float*)d_in[6];
    float* out = (float*)d_out;

    float *qf, *kf;
    __half *qh, *kh, *vh, *ctxh, *hsh, *wqt, *wkt, *wvt, *wot;
    cudaGetSymbolAddress((void**)&qf, g_q);
    cudaGetSymbolAddress((void**)&kf, g_k);
    cudaGetSymbolAddress((void**)&qh, g_qh);
    cudaGetSymbolAddress((void**)&kh, g_kh);
    cudaGetSymbolAddress((void**)&vh, g_vh);
    cudaGetSymbolAddress((void**)&ctxh, g_ctxh);
    cudaGetSymbolAddress((void**)&hsh, g_hsh);
    cudaGetSymbolAddress((void**)&wqt, g_wqt);
    cudaGetSymbolAddress((void**)&wkt, g_wkt);
    cudaGetSymbolAddress((void**)&wvt, g_wvt);
    cudaGetSymbolAddress((void**)&wot, g_wot);

    cudaFuncSetAttribute(gemm_f16_k, cudaFuncAttributeMaxDynamicSharedMemorySize,
                         G_SMEM_BYTES);
    cudaFuncSetAttribute(flash_k, cudaFuncAttributeMaxDynamicSharedMemorySize,
                         F_SMEM_BYTES);

    // Pre-pass: hs -> fp16; weights -> fp16 transposed [N][K]
    int n4 = (Mm * Dd) / 4;
    cvt_h_k<<<n4 / 256, 256>>>((const float4*)hs, (uint2*)hsh, n4);
    transpose_cvt_k<<<dim3(Dd / 32, Dd / 32), dim3(32, 8)>>>(Wq, wqt, Dd, Dd);
    transpose_cvt_k<<<dim3(NKV / 32, Dd / 32), dim3(32, 8)>>>(Wk, wkt, Dd, NKV);
    transpose_cvt_k<<<dim3(NKV / 32, Dd / 32), dim3(32, 8)>>>(Wv, wvt, Dd, NKV);
    transpose_cvt_k<<<dim3(Dd / 32, Dd / 32), dim3(32, 8)>>>(Wo, wot, Dd, Dd);

    // QKV projections: q,k -> f32 (rope follows), v -> fp16 directly
    gemm_f16_k<<<dim3(Dd / 128, Mm / 128), 256, G_SMEM_BYTES>>>(hsh, wqt, qf, nullptr, Mm, Dd, Dd);
    gemm_f16_k<<<dim3(NKV / 128, Mm / 128), 256, G_SMEM_BYTES>>>(hsh, wkt, kf, nullptr, Mm, NKV, Dd);
    gemm_f16_k<<<dim3(NKV / 128, Mm / 128), 256, G_SMEM_BYTES>>>(hsh, wvt, nullptr, vh, Mm, NKV, Dd);

    // RoPE: f32 in, fp16 out; Q gets 1/sqrt(HD) folded in
    int nq = Mm * Hh * 64;
    int nk = Mm * HKVn * 64;
    rope_h_k<<<(nq + 255) / 256, 256>>>(qf, qh, pos, Hh, nq, 0.08838834764831845f);
    rope_h_k<<<(nk + 255) / 256, 256>>>(kf, kh, pos, HKVn, nk, 1.0f);

    // Attention (Q-tile 128, pipelined K/V)
    flash_k<<<dim3(Ss / 128, Bb * Hh), 256, F_SMEM_BYTES>>>(qh, kh, vh, am, ctxh);

    // Output projection (f32 out)
    gemm_f16_k<<<dim3(Dd / 128, Mm / 128), 256, G_SMEM_BYTES>>>(ctxh, wot, out, nullptr, Mm, Dd, Dd);
}

// round 16
// speedup vs baseline: 1.1451x; 1.1451x over previous
#include <cuda_runtime.h>
#include <cuda_fp16.h>
#include <cstdint>

#define Bb 2
#define Ss 2048
#define Dd 4096
#define Hh 32
#define HKVn 8
#define HDd 128
#define Mm (Bb*Ss)
#define NKV (HKVn*HDd)

// Scratch (device globals: allocation-free)
__device__ float  g_q[(size_t)Mm * Dd];       // f32 q (pre-rope)
__device__ float  g_k[(size_t)Mm * NKV];      // f32 k (pre-rope)
__device__ __half g_qh[(size_t)Mm * Dd];      // fp16 q (post-rope, scaled)
__device__ __half g_kh[(size_t)Mm * NKV];     // fp16 k (post-rope)
__device__ __half g_vh[(size_t)Mm * NKV];     // fp16 v
__device__ __half g_ctxh[(size_t)Mm * Dd];
__device__ __half g_hsh[(size_t)Mm * Dd];     // fp16 hidden_states
__device__ __half g_wqh[(size_t)Dd * Dd];     // fp16 W, same [K][N] layout
__device__ __half g_wkh[(size_t)Dd * NKV];
__device__ __half g_wvh[(size_t)Dd * NKV];
__device__ __half g_woh[(size_t)Dd * Dd];

__device__ __forceinline__ void mma_f16(float* c, const unsigned* a, const unsigned* b) {
    asm volatile(
        "mma.sync.aligned.m16n8k16.row.col.f32.f16.f16.f32 "
        "{%0,%1,%2,%3}, {%4,%5,%6,%7}, {%8,%9}, {%0,%1,%2,%3};"
        : "+f"(c[0]), "+f"(c[1]), "+f"(c[2]), "+f"(c[3])
        : "r"(a[0]), "r"(a[1]), "r"(a[2]), "r"(a[3]), "r"(b[0]), "r"(b[1]));
}

__device__ __forceinline__ void ldsm4(unsigned& r0, unsigned& r1, unsigned& r2,
                                      unsigned& r3, unsigned addr) {
    asm volatile("ldmatrix.sync.aligned.m8n8.x4.shared.b16 {%0,%1,%2,%3}, [%4];"
                 : "=r"(r0), "=r"(r1), "=r"(r2), "=r"(r3) : "r"(addr));
}
__device__ __forceinline__ void ldsm4t(unsigned& r0, unsigned& r1, unsigned& r2,
                                       unsigned& r3, unsigned addr) {
    asm volatile("ldmatrix.sync.aligned.m8n8.x4.trans.shared.b16 {%0,%1,%2,%3}, [%4];"
                 : "=r"(r0), "=r"(r1), "=r"(r2), "=r"(r3) : "r"(addr));
}

__device__ __forceinline__ void cp16s(uint32_t dst, const void* src) {
    asm volatile("cp.async.cg.shared.global [%0], [%1], 16;" :: "r"(dst), "l"(src));
}
__device__ __forceinline__ void cp_commit() {
    asm volatile("cp.async.commit_group;" ::: "memory");
}
template <int N>
__device__ __forceinline__ void cp_wait() {
    asm volatile("cp.async.wait_group %0;" :: "n"(N) : "memory");
}

// ---------------------------------------------------------------------------
// Pre-pass: straight f32 -> fp16 streaming copy (no transpose).
// ---------------------------------------------------------------------------
__global__ void cvt_h_k(const float4* __restrict__ in, uint2* __restrict__ out, int n4) {
    int i = blockIdx.x * blockDim.x + threadIdx.x;
    if (i >= n4) return;
    float4 v = in[i];
    __half2 h0 = __floats2half2_rn(v.x, v.y);
    __half2 h1 = __floats2half2_rn(v.z, v.w);
    uint2 u = {*(unsigned*)&h0, *(unsigned*)&h1};
    out[i] = u;
}

// ---------------------------------------------------------------------------
// fp16 GEMM: C = A[M,K] @ W[K,N]; A, W fp16 row-major (natural layouts).
// Output: f32 (Cf) or fp16 (Ch) selected by Ch != nullptr.
// Block 128x128, BK=32, 256 threads (8 warps, 64x32 warp tile), occupancy 2.
// 3-stage cp.async ring, lookahead 1, SINGLE barrier per K-step.
// B fragments from [K][N] tiles via ldmatrix.trans (same pattern as flash P@V).
// ---------------------------------------------------------------------------
#define A_STR 40
#define B_STR 136
#define A_STAGE_B (128 * A_STR * 2)               // 10240
#define B_STAGE_B (32 * B_STR * 2)                // 8704
#define G_SMEM_BYTES (3 * (A_STAGE_B + B_STAGE_B))  // 56832

__global__ __launch_bounds__(256, 2) void gemm_f16_k(
    const __half* __restrict__ A, const __half* __restrict__ W,
    float* __restrict__ Cf, __half* __restrict__ Ch, int M, int N, int K) {
    extern __shared__ char smem[];
    const uint32_t sb = (uint32_t)__cvta_generic_to_shared(smem);
    const uint32_t sbA = sb, sbB = sb + 3 * A_STAGE_B;

    const int bm = blockIdx.y * 128, bn = blockIdx.x * 128;
    const int tid = threadIdx.x, warp = tid >> 5, lane = tid & 31;
    const int wm = (warp >> 2) * 64, wn = (warp & 3) * 32;
    const int g = lane >> 2, t = lane & 3;

    const int arow = lane & 15, acol = (lane >> 4) << 3;   // ldsm4 / ldsm4t geometry

    // cp.async geometry: A 512 chunks (2/thread); B 512 chunks (2/thread)
    int rA[2], cA[2], rB[2], cB[2];
#pragma unroll
    for (int j = 0; j < 2; j++) {
        int id = tid + j * 256;
        rA[j] = id >> 2;  cA[j] = (id & 3) << 3;   // A: 128 rows x 32 halves
        rB[j] = id >> 4;  cB[j] = (id & 15) << 3;  // B: 32 rows x 128 halves
    }

    float acc[4][4][4];
#pragma unroll
    for (int mt = 0; mt < 4; mt++)
#pragma unroll
        for (int nt = 0; nt < 4; nt++)
#pragma unroll
            for (int i = 0; i < 4; i++) acc[mt][nt][i] = 0.f;

    auto load_stage = [&](int k0, int s) {
#pragma unroll
        for (int j = 0; j < 2; j++) {
            cp16s(sbA + s * A_STAGE_B + (rA[j] * A_STR + cA[j]) * 2,
                  A + (size_t)(bm + rA[j]) * K + k0 + cA[j]);
            cp16s(sbB + s * B_STAGE_B + (rB[j] * B_STR + cB[j]) * 2,
                  W + (size_t)(k0 + rB[j]) * N + bn + cB[j]);
        }
        cp_commit();
    };

    load_stage(0, 0);

    const int niter = K / 32;
    for (int it = 0; it < niter; it++) {
        if (it + 1 < niter) { load_stage((it + 1) * 32, (it + 1) % 3); cp_wait<1>(); }
        else cp_wait<0>();
        __syncthreads();   // single barrier per K-step (3-stage ring makes the
                           // trailing barrier redundant: load(it+1) overwrites a
                           // stage whose readers finished before barrier(it-1))

        const uint32_t cAs = sbA + (it % 3) * A_STAGE_B;
        const uint32_t cBs = sbB + (it % 3) * B_STAGE_B;
#pragma unroll
        for (int kk = 0; kk < 32; kk += 16) {
            unsigned a[4][4], b[2][4];
#pragma unroll
            for (int mt = 0; mt < 4; mt++)
                ldsm4(a[mt][0], a[mt][1], a[mt][2], a[mt][3],
                      cAs + ((wm + mt * 16 + arow) * A_STR + kk + acol) * 2);
#pragma unroll
            for (int p = 0; p < 2; p++)
                ldsm4t(b[p][0], b[p][1], b[p][2], b[p][3],
                       cBs + ((kk + arow) * B_STR + wn + p * 16 + acol) * 2);
#pragma unroll
            for (int mt = 0; mt < 4; mt++)
#pragma unroll
                for (int nt = 0; nt < 4; nt++) {
                    unsigned bb[2] = {b[nt >> 1][(nt & 1) * 2],
                                      b[nt >> 1][(nt & 1) * 2 + 1]};
                    mma_f16(acc[mt][nt], a[mt], bb);
                }
        }
    }

#pragma unroll
    for (int mt = 0; mt < 4; mt++)
#pragma unroll
        for (int nt = 0; nt < 4; nt++) {
            int r0 = bm + wm + mt * 16 + g;
            int c0 = bn + wn + nt * 8 + 2 * t;
            if (Ch) {
                *(__half2*)&Ch[(size_t)r0 * N + c0] =
                    __floats2half2_rn(acc[mt][nt][0], acc[mt][nt][1]);
                *(__half2*)&Ch[(size_t)(r0 + 8) * N + c0] =
                    __floats2half2_rn(acc[mt][nt][2], acc[mt][nt][3]);
            } else {
                float2 v0 = {acc[mt][nt][0], acc[mt][nt][1]};
                float2 v1 = {acc[mt][nt][2], acc[mt][nt][3]};
                *(float2*)&Cf[(size_t)r0 * N + c0] = v0;
                *(float2*)&Cf[(size_t)(r0 + 8) * N + c0] = v1;
            }
        }
}

// ---------------------------------------------------------------------------
// RoPE (NeoX, half=64): reads f32 [B*S, nh, 128], writes fp16 (scale folded).
// ---------------------------------------------------------------------------
__global__ void rope_h_k(const float* __restrict__ x, __half* __restrict__ out,
                         const int* __restrict__ pos, int nh, int total, float scale) {
    int i = blockIdx.x * blockDim.x + threadIdx.x;
    if (i >= total) return;
    int j = i & 63;
    int h = (i >> 6) % nh;
    int row = i / (64 * nh);
    float p = (float)pos[row];
    float fr = p * exp2f(-(float)j * 0.20762050593046062f);
    float sn, cs;
    sincosf(fr, &sn, &cs);
    size_t base = ((size_t)row * nh + h) * 128 + j;
    float v1 = x[base] * scale, v2 = x[base + 64] * scale;
    out[base] = __float2half_rn(v1 * cs - v2 * sn);
    out[base + 64] = __float2half_rn(v2 * cs + v1 * sn);
}

// ---------------------------------------------------------------------------
// Flash attention (R10 config): fp16 in gmem, ldmatrix, K-tile 64, causal +
// key mask, GQA. Grid: (S/64 q-tiles, B*H). Block: 128 threads (4 warps).
// ---------------------------------------------------------------------------
#define FQ_STR 136
#define FP_STR 72
#define F_OFF_K (64 * FQ_STR)
#define F_OFF_V (2 * 64 * FQ_STR)
#define F_OFF_P (3 * 64 * FQ_STR)
#define F_HALVES (3 * 64 * FQ_STR + 64 * FP_STR)
#define F_SMEM_BYTES (F_HALVES * 2 + 64 * 4)

__global__ __launch_bounds__(128) void flash_k(
    const __half* __restrict__ q, const __half* __restrict__ k,
    const __half* __restrict__ v, const int* __restrict__ am,
    __half* __restrict__ ctx) {
    extern __shared__ char smem[];
    __half* Qs = (__half*)smem;
    __half* Ks = Qs + F_OFF_K;
    __half* Vs = Qs + F_OFF_V;
    __half* Ps = Qs + F_OFF_P;
    int* km = (int*)(smem + F_HALVES * 2);
    const uint32_t sb = (uint32_t)__cvta_generic_to_shared(smem);

    const int bh = blockIdx.y;
    const int b = bh >> 5, h = bh & 31, hk = h >> 2;
    const int q0 = blockIdx.x * 64;
    const int tid = threadIdx.x, warp = tid >> 5, lane = tid & 31;
    const int g = lane >> 2, t = lane & 3;
    const int arow = lane & 15, acol = (lane >> 4) << 3;
    const int brow = (((lane >> 4) & 1) << 3) + (lane & 7);
    const int bcol = ((lane >> 3) & 1) << 3;

    // Load Q tile (64x128 fp16)
#pragma unroll
    for (int i = 0; i < 8; i++) {
        int idx = tid + i * 128;
        int r = idx >> 4, c = (idx & 15) << 3;
        *(uint4*)&Qs[r * FQ_STR + c] =
            *(const uint4*)(q + ((size_t)(b * Ss + q0 + r) * Hh + h) * HDd + c);
    }

    float o[16][4];
#pragma unroll
    for (int nt = 0; nt < 16; nt++)
#pragma unroll
        for (int i = 0; i < 4; i++) o[nt][i] = 0.f;
    float mrow0 = -1e30f, mrow1 = -1e30f, lrow0 = 0.f, lrow1 = 0.f;

    const int nkt = blockIdx.x + 1;
    const int qrow0 = q0 + warp * 16 + g, qrow1 = qrow0 + 8;
    const int r0 = warp * 16;

    for (int kt = 0; kt < nkt; kt++) {
        __syncthreads();
#pragma unroll
        for (int i = 0; i < 8; i++) {
            int idx = tid + i * 128;
            int r = idx >> 4, c = (idx & 15) << 3;
            size_t base = ((size_t)(b * Ss + kt * 64 + r) * HKVn + hk) * HDd + c;
            *(uint4*)&Ks[r * FQ_STR + c] = *(const uint4*)(k + base);
            *(uint4*)&Vs[r * FQ_STR + c] = *(const uint4*)(v + base);
        }
        if (tid < 64) km[tid] = am[b * Ss + kt * 64 + tid];
        __syncthreads();

        // S = Q K^T : 16 q-rows x 64 keys per warp
        float s[8][4];
#pragma unroll
        for (int nt = 0; nt < 8; nt++)
#pragma unroll
            for (int i = 0; i < 4; i++) s[nt][i] = 0.f;
#pragma unroll
        for (int d16 = 0; d16 < 128; d16 += 16) {
            unsigned a[4], bq[4][4];
            ldsm4(a[0], a[1], a[2], a[3],
                  sb + ((r0 + arow) * FQ_STR + d16 + acol) * 2);
#pragma unroll
            for (int p = 0; p < 4; p++)
                ldsm4(bq[p][0], bq[p][1], bq[p][2], bq[p][3],
                      sb + (F_OFF_K + (p * 16 + brow) * FQ_STR + d16 + bcol) * 2);
#pragma unroll
            for (int nt = 0; nt < 8; nt++) {
                unsigned bb[2] = {bq[nt >> 1][(nt & 1) * 2],
                                  bq[nt >> 1][(nt & 1) * 2 + 1]};
                mma_f16(s[nt], a, bb);
            }
        }

        // Causal + key mask, online softmax
        float mx0 = -1e30f, mx1 = -1e30f;
#pragma unroll
        for (int nt = 0; nt < 8; nt++) {
            int cl = nt * 8 + 2 * t;
            int c0 = kt * 64 + cl;
            int m0 = km[cl], m1 = km[cl + 1];
            if (c0 > qrow0 || m0 == 0) s[nt][0] = -1e30f;
            if (c0 + 1 > qrow0 || m1 == 0) s[nt][1] = -1e30f;
            if (c0 > qrow1 || m0 == 0) s[nt][2] = -1e30f;
            if (c0 + 1 > qrow1 || m1 == 0) s[nt][3] = -1e30f;
            mx0 = fmaxf(mx0, fmaxf(s[nt][0], s[nt][1]));
            mx1 = fmaxf(mx1, fmaxf(s[nt][2], s[nt][3]));
        }
        mx0 = fmaxf(mx0, __shfl_xor_sync(0xffffffffu, mx0, 1));
        mx0 = fmaxf(mx0, __shfl_xor_sync(0xffffffffu, mx0, 2));
        mx1 = fmaxf(mx1, __shfl_xor_sync(0xffffffffu, mx1, 1));
        mx1 = fmaxf(mx1, __shfl_xor_sync(0xffffffffu, mx1, 2));

        float nm0 = fmaxf(mrow0, mx0), nm1 = fmaxf(mrow1, mx1);
        float al0 = __expf(mrow0 - nm0), al1 = __expf(mrow1 - nm1);
        mrow0 = nm0; mrow1 = nm1;

        float sum0 = 0.f, sum1 = 0.f;
#pragma unroll
        for (int nt = 0; nt < 8; nt++) {
            s[nt][0] = __expf(s[nt][0] - nm0);
            s[nt][1] = __expf(s[nt][1] - nm0);
            s[nt][2] = __expf(s[nt][2] - nm1);
            s[nt][3] = __expf(s[nt][3] - nm1);
            sum0 += s[nt][0] + s[nt][1];
            sum1 += s[nt][2] + s[nt][3];
        }
        sum0 += __shfl_xor_sync(0xffffffffu, sum0, 1);
        sum0 += __shfl_xor_sync(0xffffffffu, sum0, 2);
        sum1 += __shfl_xor_sync(0xffffffffu, sum1, 1);
        sum1 += __shfl_xor_sync(0xffffffffu, sum1, 2);
        lrow0 = lrow0 * al0 + sum0;
        lrow1 = lrow1 * al1 + sum1;

#pragma unroll
        for (int nt = 0; nt < 16; nt++) {
            o[nt][0] *= al0; o[nt][1] *= al0;
            o[nt][2] *= al1; o[nt][3] *= al1;
        }

        // Stage P (fp16) to warp-private smem rows
        __syncwarp();
#pragma unroll
        for (int nt = 0; nt < 8; nt++) {
            *(__half2*)&Ps[(r0 + g) * FP_STR + nt * 8 + 2 * t] =
                __floats2half2_rn(s[nt][0], s[nt][1]);
            *(__half2*)&Ps[(r0 + g + 8) * FP_STR + nt * 8 + 2 * t] =
                __floats2half2_rn(s[nt][2], s[nt][3]);
        }
        __syncwarp();

        // O += P @ V  (keys 64 in 4 steps of 16; V^T frags via ldmatrix.trans)
#pragma unroll
        for (int kk = 0; kk < 64; kk += 16) {
            unsigned a[4], bv[8][4];
            ldsm4(a[0], a[1], a[2], a[3],
                  sb + (F_OFF_P + (r0 + arow) * FP_STR + kk + acol) * 2);
#pragma unroll
            for (int p = 0; p < 8; p++)
                ldsm4t(bv[p][0], bv[p][1], bv[p][2], bv[p][3],
                       sb + (F_OFF_V + (kk + arow) * FQ_STR + p * 16 + acol) * 2);
#pragma unroll
            for (int nt = 0; nt < 16; nt++) {
                unsigned bb[2] = {bv[nt >> 1][(nt & 1) * 2],
                                  bv[nt >> 1][(nt & 1) * 2 + 1]};
                mma_f16(o[nt], a, bb);
            }
        }
    }

    // Finalize, write ctx fp16 [B*S, H*HD]
    float il0 = 1.f / lrow0, il1 = 1.f / lrow1;
    int rq = q0 + r0 + g;
#pragma unroll
    for (int nt = 0; nt < 16; nt++) {
        int c = h * 128 + nt * 8 + 2 * t;
        *(__half2*)&ctx[(size_t)(b * Ss + rq) * Dd + c] =
            __floats2half2_rn(o[nt][0] * il0, o[nt][1] * il0);
        *(__half2*)&ctx[(size_t)(b * Ss + rq + 8) * Dd + c] =
            __floats2half2_rn(o[nt][2] * il1, o[nt][3] * il1);
    }
}

// ---------------------------------------------------------------------------
extern "C" void kernel_launch(void* const* d_in, const int* in_sizes, int n_in,
                              void* d_out, int out_size) {
    const float* hs = (const float*)d_in[0];
    const int* pos = (const int*)d_in[1];
    const int* am = (const int*)d_in[2];
    const float* Wq = (const float*)d_in[3];
    const float* Wk = (const float*)d_in[4];
    const float* Wv = (const float*)d_in[5];
    const float* Wo = (const float*)d_in[6];
    float* out = (float*)d_out;

    float *qf, *kf;
    __half *qh, *kh, *vh, *ctxh, *hsh, *wqh, *wkh, *wvh, *woh;
    cudaGetSymbolAddress((void**)&qf, g_q);
    cudaGetSymbolAddress((void**)&kf, g_k);
    cudaGetSymbolAddress((void**)&qh, g_qh);
    cudaGetSymbolAddress((void**)&kh, g_kh);
    cudaGetSymbolAddress((void**)&vh, g_vh);
    cudaGetSymbolAddress((void**)&ctxh, g_ctxh);
    cudaGetSymbolAddress((void**)&hsh, g_hsh);
    cudaGetSymbolAddress((void**)&wqh, g_wqh);
    cudaGetSymbolAddress((void**)&wkh, g_wkh);
    cudaGetSymbolAddress((void**)&wvh, g_wvh);
    cudaGetSymbolAddress((void**)&woh, g_woh);

    cudaFuncSetAttribute(gemm_f16_k, cudaFuncAttributeMaxDynamicSharedMemorySize,
                         G_SMEM_BYTES);
    cudaFuncSetAttribute(flash_k, cudaFuncAttributeMaxDynamicSharedMemorySize,
                         F_SMEM_BYTES);

    // Pre-pass: straight f32 -> fp16 copies (layouts unchanged)
    cvt_h_k<<<(Mm * Dd / 4) / 256, 256>>>((const float4*)hs, (uint2*)hsh, Mm * Dd / 4);
    cvt_h_k<<<(Dd * Dd / 4) / 256, 256>>>((const float4*)Wq, (uint2*)wqh, Dd * Dd / 4);
    cvt_h_k<<<(Dd * NKV / 4) / 256, 256>>>((const float4*)Wk, (uint2*)wkh, Dd * NKV / 4);
    cvt_h_k<<<(Dd * NKV / 4) / 256, 256>>>((const float4*)Wv, (uint2*)wvh, Dd * NKV / 4);
    cvt_h_k<<<(Dd * Dd / 4) / 256, 256>>>((const float4*)Wo, (uint2*)woh, Dd * Dd / 4);

    // QKV projections: q,k -> f32 (rope follows), v -> fp16 directly
    gemm_f16_k<<<dim3(Dd / 128, Mm / 128), 256, G_SMEM_BYTES>>>(hsh, wqh, qf, nullptr, Mm, Dd, Dd);
    gemm_f16_k<<<dim3(NKV / 128, Mm / 128), 256, G_SMEM_BYTES>>>(hsh, wkh, kf, nullptr, Mm, NKV, Dd);
    gemm_f16_k<<<dim3(NKV / 128, Mm / 128), 256, G_SMEM_BYTES>>>(hsh, wvh, nullptr, vh, Mm, NKV, Dd);

    // RoPE: f32 in, fp16 out; Q gets 1/sqrt(HD) folded in
    int nq = Mm * Hh * 64;
    int nk = Mm * HKVn * 64;
    rope_h_k<<<(nq + 255) / 256, 256>>>(qf, qh, pos, Hh, nq, 0.08838834764831845f);
    rope_h_k<<<(nk + 255) / 256, 256>>>(kf, kh, pos, HKVn, nk, 1.0f);

    // Attention (R10 config)
    flash_k<<<dim3(Ss / 64, Bb * Hh), 128, F_SMEM_BYTES>>>(qh, kh, vh, am, ctxh);

    // Output projection (f32 out)
    gemm_f16_k<<<dim3(Dd / 128, Mm / 128), 256, G_SMEM_BYTES>>>(ctxh, woh, out, nullptr, Mm, Dd, Dd);
}

// round 17
// speedup vs baseline: 1.7101x; 1.4934x over previous
#include <cuda_runtime.h>
#include <cuda_fp16.h>
#include <cstdint>

#define Bb 2
#define Ss 2048
#define Dd 4096
#define Hh 32
#define HKVn 8
#define HDd 128
#define Mm (Bb*Ss)
#define NKV (HKVn*HDd)

// Scratch (device globals: allocation-free)
__device__ __half g_qh[(size_t)Mm * Dd];      // fp16 q (GEMM out; rope in-place)
__device__ __half g_kh[(size_t)Mm * NKV];     // fp16 k (GEMM out; rope in-place)
__device__ __half g_vh[(size_t)Mm * NKV];     // fp16 v
__device__ __half g_ctxh[(size_t)Mm * Dd];
__device__ __half g_hsh[(size_t)Mm * Dd];     // fp16 hidden_states
__device__ __half g_wqt[(size_t)Dd * Dd];     // fp16 W^T (K-major, [N][K])
__device__ __half g_wkt[(size_t)NKV * Dd];
__device__ __half g_wvt[(size_t)NKV * Dd];
__device__ __half g_wot[(size_t)Dd * Dd];

__device__ __forceinline__ void mma_f16(float* c, const unsigned* a, const unsigned* b) {
    asm volatile(
        "mma.sync.aligned.m16n8k16.row.col.f32.f16.f16.f32 "
        "{%0,%1,%2,%3}, {%4,%5,%6,%7}, {%8,%9}, {%0,%1,%2,%3};"
        : "+f"(c[0]), "+f"(c[1]), "+f"(c[2]), "+f"(c[3])
        : "r"(a[0]), "r"(a[1]), "r"(a[2]), "r"(a[3]), "r"(b[0]), "r"(b[1]));
}

__device__ __forceinline__ void ldsm4(unsigned& r0, unsigned& r1, unsigned& r2,
                                      unsigned& r3, unsigned addr) {
    asm volatile("ldmatrix.sync.aligned.m8n8.x4.shared.b16 {%0,%1,%2,%3}, [%4];"
                 : "=r"(r0), "=r"(r1), "=r"(r2), "=r"(r3) : "r"(addr));
}
__device__ __forceinline__ void ldsm4t(unsigned& r0, unsigned& r1, unsigned& r2,
                                       unsigned& r3, unsigned addr) {
    asm volatile("ldmatrix.sync.aligned.m8n8.x4.trans.shared.b16 {%0,%1,%2,%3}, [%4];"
                 : "=r"(r0), "=r"(r1), "=r"(r2), "=r"(r3) : "r"(addr));
}

__device__ __forceinline__ void cp16s(uint32_t dst, const void* src) {
    asm volatile("cp.async.cg.shared.global [%0], [%1], 16;" :: "r"(dst), "l"(src));
}
__device__ __forceinline__ void cp_commit() {
    asm volatile("cp.async.commit_group;" ::: "memory");
}
template <int N>
__device__ __forceinline__ void cp_wait() {
    asm volatile("cp.async.wait_group %0;" :: "n"(N) : "memory");
}

// ---------------------------------------------------------------------------
// Pre-pass: f32 -> fp16 copy, and f32 -> fp16 transpose (W[K,N] -> Wt[N,K]).
// ---------------------------------------------------------------------------
__global__ void cvt_h_k(const float4* __restrict__ in, uint2* __restrict__ out, int n4) {
    int i = blockIdx.x * blockDim.x + threadIdx.x;
    if (i >= n4) return;
    float4 v = in[i];
    __half2 h0 = __floats2half2_rn(v.x, v.y);
    __half2 h1 = __floats2half2_rn(v.z, v.w);
    uint2 u = {*(unsigned*)&h0, *(unsigned*)&h1};
    out[i] = u;
}

__global__ void transpose_cvt_k(const float* __restrict__ in, __half* __restrict__ out,
                                int R, int C) {   // in[R][C] -> out[C][R]
    __shared__ float t[32][33];
    int x = blockIdx.x * 32 + threadIdx.x;
    int y = blockIdx.y * 32 + threadIdx.y;
#pragma unroll
    for (int j = 0; j < 32; j += 8)
        t[threadIdx.y + j][threadIdx.x] = in[(size_t)(y + j) * C + x];
    __syncthreads();
    int x2 = blockIdx.y * 32 + threadIdx.x;
    int y2 = blockIdx.x * 32 + threadIdx.y;
#pragma unroll
    for (int j = 0; j < 32; j += 8)
        out[(size_t)(y2 + j) * R + x2] = __float2half_rn(t[threadIdx.x][threadIdx.y + j]);
}

// ---------------------------------------------------------------------------
// fp16 GEMM (R10 config, single barrier per K-step):
// C = A[M,K] @ Bt[N,K]^T; A/Bt fp16 row-major.
// Block 128x128, BK=32, 256 threads (8 warps, 64x32 warp tile), occupancy 2.
// 3-stage cp.async ring, lookahead 1, ldmatrix (non-trans) frags only.
// ---------------------------------------------------------------------------
#define GA_STRIDE 40
#define GA_STAGE_B (128 * GA_STRIDE * 2)          // bytes per stage per operand
#define G_SMEM_BYTES (6 * GA_STAGE_B)             // 61440

__global__ __launch_bounds__(256, 2) void gemm_f16_k(
    const __half* __restrict__ A, const __half* __restrict__ Bt,
    float* __restrict__ Cf, __half* __restrict__ Ch, int M, int N, int K) {
    extern __shared__ char smem[];
    const uint32_t sb = (uint32_t)__cvta_generic_to_shared(smem);
    const uint32_t sbA = sb, sbB = sb + 3 * GA_STAGE_B;

    const int bm = blockIdx.y * 128, bn = blockIdx.x * 128;
    const int tid = threadIdx.x, warp = tid >> 5, lane = tid & 31;
    const int wm = (warp >> 2) * 64, wn = (warp & 3) * 32;
    const int g = lane >> 2, t = lane & 3;

    const int arow = lane & 15, acol = (lane >> 4) << 3;
    const int brow = (((lane >> 4) & 1) << 3) + (lane & 7);
    const int bcol = ((lane >> 3) & 1) << 3;

    int rr[2], cu[2];
#pragma unroll
    for (int j = 0; j < 2; j++) {
        int id = tid + j * 256;
        rr[j] = id >> 2;
        cu[j] = (id & 3) << 3;
    }

    float acc[4][4][4];
#pragma unroll
    for (int mt = 0; mt < 4; mt++)
#pragma unroll
        for (int nt = 0; nt < 4; nt++)
#pragma unroll
            for (int i = 0; i < 4; i++) acc[mt][nt][i] = 0.f;

    auto load_stage = [&](int k0, int s) {
#pragma unroll
        for (int j = 0; j < 2; j++) {
            cp16s(sbA + s * GA_STAGE_B + (rr[j] * GA_STRIDE + cu[j]) * 2,
                  A + (size_t)(bm + rr[j]) * K + k0 + cu[j]);
            cp16s(sbB + s * GA_STAGE_B + (rr[j] * GA_STRIDE + cu[j]) * 2,
                  Bt + (size_t)(bn + rr[j]) * K + k0 + cu[j]);
        }
        cp_commit();
    };

    load_stage(0, 0);

    const int niter = K / 32;
    for (int it = 0; it < niter; it++) {
        if (it + 1 < niter) { load_stage((it + 1) * 32, (it + 1) % 3); cp_wait<1>(); }
        else cp_wait<0>();
        __syncthreads();   // single barrier per K-step: load(it+1) overwrites a
                           // stage whose readers all finished before barrier(it-1)

        const uint32_t cA = sbA + (it % 3) * GA_STAGE_B;
        const uint32_t cB = sbB + (it % 3) * GA_STAGE_B;
#pragma unroll
        for (int kk = 0; kk < 32; kk += 16) {
            unsigned a[4][4], b[2][4];
#pragma unroll
            for (int mt = 0; mt < 4; mt++)
                ldsm4(a[mt][0], a[mt][1], a[mt][2], a[mt][3],
                      cA + ((wm + mt * 16 + arow) * GA_STRIDE + kk + acol) * 2);
#pragma unroll
            for (int p = 0; p < 2; p++)
                ldsm4(b[p][0], b[p][1], b[p][2], b[p][3],
                      cB + ((wn + p * 16 + brow) * GA_STRIDE + kk + bcol) * 2);
#pragma unroll
            for (int mt = 0; mt < 4; mt++)
#pragma unroll
                for (int nt = 0; nt < 4; nt++) {
                    unsigned bb[2] = {b[nt >> 1][(nt & 1) * 2],
                                      b[nt >> 1][(nt & 1) * 2 + 1]};
                    mma_f16(acc[mt][nt], a[mt], bb);
                }
        }
    }

#pragma unroll
    for (int mt = 0; mt < 4; mt++)
#pragma unroll
        for (int nt = 0; nt < 4; nt++) {
            int r0 = bm + wm + mt * 16 + g;
            int c0 = bn + wn + nt * 8 + 2 * t;
            if (Ch) {
                *(__half2*)&Ch[(size_t)r0 * N + c0] =
                    __floats2half2_rn(acc[mt][nt][0], acc[mt][nt][1]);
                *(__half2*)&Ch[(size_t)(r0 + 8) * N + c0] =
                    __floats2half2_rn(acc[mt][nt][2], acc[mt][nt][3]);
            } else {
                float2 v0 = {acc[mt][nt][0], acc[mt][nt][1]};
                float2 v1 = {acc[mt][nt][2], acc[mt][nt][3]};
                *(float2*)&Cf[(size_t)r0 * N + c0] = v0;
                *(float2*)&Cf[(size_t)(r0 + 8) * N + c0] = v1;
            }
        }
}

// ---------------------------------------------------------------------------
// RoPE (NeoX, half=64): in-place on fp16 [B*S, nh, 128]; each thread owns one
// rotation pair (j, j+64), so in-place is race-free. Scale folded (for Q).
// ---------------------------------------------------------------------------
__global__ void rope_h16_k(__half* __restrict__ x, const int* __restrict__ pos,
                           int nh, int total, float scale) {
    int i = blockIdx.x * blockDim.x + threadIdx.x;
    if (i >= total) return;
    int j = i & 63;
    int h = (i >> 6) % nh;
    int row = i / (64 * nh);
    float p = (float)pos[row];
    float fr = p * exp2f(-(float)j * 0.20762050593046062f);
    float sn, cs;
    sincosf(fr, &sn, &cs);
    __half* ptr = x + ((size_t)row * nh + h) * 128 + j;
    float v1 = __half2float(ptr[0]) * scale, v2 = __half2float(ptr[64]) * scale;
    ptr[0] = __float2half_rn(v1 * cs - v2 * sn);
    ptr[64] = __float2half_rn(v2 * cs + v1 * sn);
}

// ---------------------------------------------------------------------------
// Flash attention (R10 config): fp16 in gmem, ldmatrix, K-tile 64, causal +
// key mask, GQA. Grid: (S/64 q-tiles, B*H). Block: 128 threads (4 warps).
// ---------------------------------------------------------------------------
#define FQ_STR 136
#define FP_STR 72
#define F_OFF_K (64 * FQ_STR)
#define F_OFF_V (2 * 64 * FQ_STR)
#define F_OFF_P (3 * 64 * FQ_STR)
#define F_HALVES (3 * 64 * FQ_STR + 64 * FP_STR)
#define F_SMEM_BYTES (F_HALVES * 2 + 64 * 4)

__global__ __launch_bounds__(128) void flash_k(
    const __half* __restrict__ q, const __half* __restrict__ k,
    const __half* __restrict__ v, const int* __restrict__ am,
    __half* __restrict__ ctx) {
    extern __shared__ char smem[];
    __half* Qs = (__half*)smem;
    __half* Ks = Qs + F_OFF_K;
    __half* Vs = Qs + F_OFF_V;
    __half* Ps = Qs + F_OFF_P;
    int* km = (int*)(smem + F_HALVES * 2);
    const uint32_t sb = (uint32_t)__cvta_generic_to_shared(smem);

    const int bh = blockIdx.y;
    const int b = bh >> 5, h = bh & 31, hk = h >> 2;
    const int q0 = blockIdx.x * 64;
    const int tid = threadIdx.x, warp = tid >> 5, lane = tid & 31;
    const int g = lane >> 2, t = lane & 3;
    const int arow = lane & 15, acol = (lane >> 4) << 3;
    const int brow = (((lane >> 4) & 1) << 3) + (lane & 7);
    const int bcol = ((lane >> 3) & 1) << 3;

    // Load Q tile (64x128 fp16)
#pragma unroll
    for (int i = 0; i < 8; i++) {
        int idx = tid + i * 128;
        int r = idx >> 4, c = (idx & 15) << 3;
        *(uint4*)&Qs[r * FQ_STR + c] =
            *(const uint4*)(q + ((size_t)(b * Ss + q0 + r) * Hh + h) * HDd + c);
    }

    float o[16][4];
#pragma unroll
    for (int nt = 0; nt < 16; nt++)
#pragma unroll
        for (int i = 0; i < 4; i++) o[nt][i] = 0.f;
    float mrow0 = -1e30f, mrow1 = -1e30f, lrow0 = 0.f, lrow1 = 0.f;

    const int nkt = blockIdx.x + 1;
    const int qrow0 = q0 + warp * 16 + g, qrow1 = qrow0 + 8;
    const int r0 = warp * 16;

    for (int kt = 0; kt < nkt; kt++) {
        __syncthreads();
#pragma unroll
        for (int i = 0; i < 8; i++) {
            int idx = tid + i * 128;
            int r = idx >> 4, c = (idx & 15) << 3;
            size_t base = ((size_t)(b * Ss + kt * 64 + r) * HKVn + hk) * HDd + c;
            *(uint4*)&Ks[r * FQ_STR + c] = *(const uint4*)(k + base);
            *(uint4*)&Vs[r * FQ_STR + c] = *(const uint4*)(v + base);
        }
        if (tid < 64) km[tid] = am[b * Ss + kt * 64 + tid];
        __syncthreads();

        // S = Q K^T : 16 q-rows x 64 keys per warp
        float s[8][4];
#pragma unroll
        for (int nt = 0; nt < 8; nt++)
#pragma unroll
            for (int i = 0; i < 4; i++) s[nt][i] = 0.f;
#pragma unroll
        for (int d16 = 0; d16 < 128; d16 += 16) {
            unsigned a[4], bq[4][4];
            ldsm4(a[0], a[1], a[2], a[3],
                  sb + ((r0 + arow) * FQ_STR + d16 + acol) * 2);
#pragma unroll
            for (int p = 0; p < 4; p++)
                ldsm4(bq[p][0], bq[p][1], bq[p][2], bq[p][3],
                      sb + (F_OFF_K + (p * 16 + brow) * FQ_STR + d16 + bcol) * 2);
#pragma unroll
            for (int nt = 0; nt < 8; nt++) {
                unsigned bb[2] = {bq[nt >> 1][(nt & 1) * 2],
                                  bq[nt >> 1][(nt & 1) * 2 + 1]};
                mma_f16(s[nt], a, bb);
            }
        }

        // Causal + key mask, online softmax
        float mx0 = -1e30f, mx1 = -1e30f;
#pragma unroll
        for (int nt = 0; nt < 8; nt++) {
            int cl = nt * 8 + 2 * t;
            int c0 = kt * 64 + cl;
            int m0 = km[cl], m1 = km[cl + 1];
            if (c0 > qrow0 || m0 == 0) s[nt][0] = -1e30f;
            if (c0 + 1 > qrow0 || m1 == 0) s[nt][1] = -1e30f;
            if (c0 > qrow1 || m0 == 0) s[nt][2] = -1e30f;
            if (c0 + 1 > qrow1 || m1 == 0) s[nt][3] = -1e30f;
            mx0 = fmaxf(mx0, fmaxf(s[nt][0], s[nt][1]));
            mx1 = fmaxf(mx1, fmaxf(s[nt][2], s[nt][3]));
        }
        mx0 = fmaxf(mx0, __shfl_xor_sync(0xffffffffu, mx0, 1));
        mx0 = fmaxf(mx0, __shfl_xor_sync(0xffffffffu, mx0, 2));
        mx1 = fmaxf(mx1, __shfl_xor_sync(0xffffffffu, mx1, 1));
        mx1 = fmaxf(mx1, __shfl_xor_sync(0xffffffffu, mx1, 2));

        float nm0 = fmaxf(mrow0, mx0), nm1 = fmaxf(mrow1, mx1);
        float al0 = __expf(mrow0 - nm0), al1 = __expf(mrow1 - nm1);
        mrow0 = nm0; mrow1 = nm1;

        float sum0 = 0.f, sum1 = 0.f;
#pragma unroll
        for (int nt = 0; nt < 8; nt++) {
            s[nt][0] = __expf(s[nt][0] - nm0);
            s[nt][1] = __expf(s[nt][1] - nm0);
            s[nt][2] = __expf(s[nt][2] - nm1);
            s[nt][3] = __expf(s[nt][3] - nm1);
            sum0 += s[nt][0] + s[nt][1];
            sum1 += s[nt][2] + s[nt][3];
        }
        sum0 += __shfl_xor_sync(0xffffffffu, sum0, 1);
        sum0 += __shfl_xor_sync(0xffffffffu, sum0, 2);
        sum1 += __shfl_xor_sync(0xffffffffu, sum1, 1);
        sum1 += __shfl_xor_sync(0xffffffffu, sum1, 2);
        lrow0 = lrow0 * al0 + sum0;
        lrow1 = lrow1 * al1 + sum1;

#pragma unroll
        for (int nt = 0; nt < 16; nt++) {
            o[nt][0] *= al0; o[nt][1] *= al0;
            o[nt][2] *= al1; o[nt][3] *= al1;
        }

        // Stage P (fp16) to warp-private smem rows
        __syncwarp();
#pragma unroll
        for (int nt = 0; nt < 8; nt++) {
            *(__half2*)&Ps[(r0 + g) * FP_STR + nt * 8 + 2 * t] =
                __floats2half2_rn(s[nt][0], s[nt][1]);
            *(__half2*)&Ps[(r0 + g + 8) * FP_STR + nt * 8 + 2 * t] =
                __floats2half2_rn(s[nt][2], s[nt][3]);
        }
        __syncwarp();

        // O += P @ V  (keys 64 in 4 steps of 16; V^T frags via ldmatrix.trans)
#pragma unroll
        for (int kk = 0; kk < 64; kk += 16) {
            unsigned a[4], bv[8][4];
            ldsm4(a[0], a[1], a[2], a[3],
                  sb + (F_OFF_P + (r0 + arow) * FP_STR + kk + acol) * 2);
#pragma unroll
            for (int p = 0; p < 8; p++)
                ldsm4t(bv[p][0], bv[p][1], bv[p][2], bv[p][3],
                       sb + (F_OFF_V + (kk + arow) * FQ_STR + p * 16 + acol) * 2);
#pragma unroll
            for (int nt = 0; nt < 16; nt++) {
                unsigned bb[2] = {bv[nt >> 1][(nt & 1) * 2],
                                  bv[nt >> 1][(nt & 1) * 2 + 1]};
                mma_f16(o[nt], a, bb);
            }
        }
    }

    // Finalize, write ctx fp16 [B*S, H*HD]
    float il0 = 1.f / lrow0, il1 = 1.f / lrow1;
    int rq = q0 + r0 + g;
#pragma unroll
    for (int nt = 0; nt < 16; nt++) {
        int c = h * 128 + nt * 8 + 2 * t;
        *(__half2*)&ctx[(size_t)(b * Ss + rq) * Dd + c] =
            __floats2half2_rn(o[nt][0] * il0, o[nt][1] * il0);
        *(__half2*)&ctx[(size_t)(b * Ss + rq + 8) * Dd + c] =
            __floats2half2_rn(o[nt][2] * il1, o[nt][3] * il1);
    }
}

// ---------------------------------------------------------------------------
extern "C" void kernel_launch(void* const* d_in, const int* in_sizes, int n_in,
                              void* d_out, int out_size) {
    const float* hs = (const float*)d_in[0];
    const int* pos = (const int*)d_in[1];
    const int* am = (const int*)d_in[2];
    const float* Wq = (const float*)d_in[3];
    const float* Wk = (const float*)d_in[4];
    const float* Wv = (const float*)d_in[5];
    const float* Wo = (const float*)d_in[6];
    float* out = (float*)d_out;

    __half *qh, *kh, *vh, *ctxh, *hsh, *wqt, *wkt, *wvt, *wot;
    cudaGetSymbolAddress((void**)&qh, g_qh);
    cudaGetSymbolAddress((void**)&kh, g_kh);
    cudaGetSymbolAddress((void**)&vh, g_vh);
    cudaGetSymbolAddress((void**)&ctxh, g_ctxh);
    cudaGetSymbolAddress((void**)&hsh, g_hsh);
    cudaGetSymbolAddress((void**)&wqt, g_wqt);
    cudaGetSymbolAddress((void**)&wkt, g_wkt);
    cudaGetSymbolAddress((void**)&wvt, g_wvt);
    cudaGetSymbolAddress((void**)&wot, g_wot);

    cudaFuncSetAttribute(gemm_f16_k, cudaFuncAttributeMaxDynamicSharedMemorySize,
                         G_SMEM_BYTES);
    cudaFuncSetAttribute(flash_k, cudaFuncAttributeMaxDynamicSharedMemorySize,
                         F_SMEM_BYTES);

    // Pre-pass: hs -> fp16; weights -> fp16 transposed [N][K]
    int n4 = (Mm * Dd) / 4;
    cvt_h_k<<<n4 / 256, 256>>>((const float4*)hs, (uint2*)hsh, n4);
    transpose_cvt_k<<<dim3(Dd / 32, Dd / 32), dim3(32, 8)>>>(Wq, wqt, Dd, Dd);
    transpose_cvt_k<<<dim3(NKV / 32, Dd / 32), dim3(32, 8)>>>(Wk, wkt, Dd, NKV);
    transpose_cvt_k<<<dim3(NKV / 32, Dd / 32), dim3(32, 8)>>>(Wv, wvt, Dd, NKV);
    transpose_cvt_k<<<dim3(Dd / 32, Dd / 32), dim3(32, 8)>>>(Wo, wot, Dd, Dd);

    // QKV projections: all fp16 out (rope runs in-place on q/k)
    gemm_f16_k<<<dim3(Dd / 128, Mm / 128), 256, G_SMEM_BYTES>>>(hsh, wqt, nullptr, qh, Mm, Dd, Dd);
    gemm_f16_k<<<dim3(NKV / 128, Mm / 128), 256, G_SMEM_BYTES>>>(hsh, wkt, nullptr, kh, Mm, NKV, Dd);
    gemm_f16_k<<<dim3(NKV / 128, Mm / 128), 256, G_SMEM_BYTES>>>(hsh, wvt, nullptr, vh, Mm, NKV, Dd);

    // RoPE in-place on fp16; Q gets 1/sqrt(HD) folded in
    int nq = Mm * Hh * 64;
    int nk = Mm * HKVn * 64;
    rope_h16_k<<<(nq + 255) / 256, 256>>>(qh, pos, Hh, nq, 0.08838834764831845f);
    rope_h16_k<<<(nk + 255) / 256, 256>>>(kh, pos, HKVn, nk, 1.0f);

    // Attention (R10 config)
    flash_k<<<dim3(Ss / 64, Bb * Hh), 128, F_SMEM_BYTES>>>(qh, kh, vh, am, ctxh);

    // Output projection (f32 out)
    gemm_f16_k<<<dim3(Dd / 128, Mm / 128), 256, G_SMEM_BYTES>>>(ctxh, wot, out, nullptr, Mm, Dd, Dd);
}